// round 3
// baseline (speedup 1.0000x reference)
#include <cuda_runtime.h>
#include <cuda_bf16.h>

#define NB   2
#define NPT  2048
#define NLAT 512
#define CCH  32
#define INC  16

// scratch for lifted features f[b, n, c]
__device__ float g_f[NB * NPT * CCH];

// jax.nn.gelu(approximate=True) == x * sigmoid(2*sqrt(2/pi)*(x + 0.044715 x^3))
__device__ __forceinline__ float gelu_f(float x) {
    float x3 = x * x * x;
    float z = 1.5957691216057308f * fmaf(0.044715f, x3, x);
    return x / (1.0f + __expf(-z));
}

__global__ void lift_kernel(const float* __restrict__ pndata,
                            const float* __restrict__ W,
                            const float* __restrict__ bias) {
    int idx = blockIdx.x * blockDim.x + threadIdx.x;
    if (idx >= NB * NPT * CCH) return;
    int c = idx & 31;
    int row = idx >> 5;
    const float* p = pndata + row * INC;
    float s = bias[c];
#pragma unroll
    for (int k = 0; k < INC; k++) s = fmaf(p[k], W[k * CCH + c], s);
    g_f[idx] = s;
}

__global__ void __launch_bounds__(128) agg_kernel(
    const float* __restrict__ x_coord,
    const float* __restrict__ ltc,
    const float* __restrict__ kW1, const float* __restrict__ kb1,
    const float* __restrict__ kW2, const float* __restrict__ kb2,
    const float* __restrict__ kW3, const float* __restrict__ kb3,
    float* __restrict__ out)
{
    __shared__ float sW1[128], sb1[32], sW2[1024], sb2[32], sW3[1024], sb3[32];
    __shared__ int   slist[NPT];           // per-warp segmented compact list
    __shared__ int   swcnt[4], swcnt1[4], soff[5];
    __shared__ float sacc[128][8];         // per-thread partial accumulators

    const int tid  = threadIdx.x;
    const int wid  = tid >> 5;
    const int lane = tid & 31;
    const int bi   = blockIdx.x;           // = b*NLAT + i
    const int b    = bi >> 9;
    const int i    = bi & (NLAT - 1);

    // load weights to shared
    sW1[tid] = kW1[tid];
    for (int t = tid; t < 1024; t += 128) { sW2[t] = kW2[t]; sW3[t] = kW3[t]; }
    if (tid < 32) { sb1[tid] = kb1[tid]; sb2[tid] = kb2[tid]; sb3[tid] = kb3[tid]; }

    const float2 xq = ((const float2*)ltc)[i];
    const float R1SQ = (float)(0.07 * 0.07);   // matches jax f32(double) constants
    const float R2SQ = (float)(0.14 * 0.14);

    // ---- Phase A: deterministic ballot compaction, per-warp j segments ----
    const float2* xc2 = (const float2*)x_coord + (size_t)b * NPT;
    const int wbase = wid * 512;
    int wcount = 0, wcount1 = 0;
    for (int jj = lane; jj < 512; jj += 32) {
        int j = wbase + jj;
        float2 y = xc2[j];
        float d0 = y.x - xq.x;
        float d1 = y.y - xq.y;
        // exact match to jax: d0*d0 + d1*d1 with NO fma contraction
        float d2 = __fadd_rn(__fmul_rn(d0, d0), __fmul_rn(d1, d1));
        bool sel = (d2 <= R2SQ);
        bool in1 = (d2 <= R1SQ);
        unsigned bal = __ballot_sync(0xffffffffu, sel);
        if (sel) {
            int pos = wcount + __popc(bal & ((1u << lane) - 1u));
            slist[wbase + pos] = j | ((int)in1 << 12);
        }
        wcount  += __popc(bal);
        wcount1 += __popc(__ballot_sync(0xffffffffu, in1));
    }
    if (lane == 0) { swcnt[wid] = wcount; swcnt1[wid] = wcount1; }
    __syncthreads();
    if (tid == 0) {
        int o = 0;
#pragma unroll
        for (int w = 0; w < 4; w++) { soff[w] = o; o += swcnt[w]; }
        soff[4] = o;
        swcnt1[0] = swcnt1[0] + swcnt1[1] + swcnt1[2] + swcnt1[3];
    }
    __syncthreads();

    const int   m    = soff[4];
    const int   c1   = swcnt1[0];
    const float inv2 = 1.0f / fmaxf((float)m,  1.0f);
    const float inv1 = 1.0f / fmaxf((float)c1, 1.0f);
    const float w12  = inv1 + inv2;
    const int o1 = soff[1], o2 = soff[2], o3 = soff[3];

    // ---- Phase B: quad-per-pair MLP; lane owns 8 of 32 channels ----
    const int      qg    = tid >> 2;                 // global quad id (0..31)
    const int      qid   = tid & 3;                  // lane in quad -> channel group
    const int      cbase = qid * 8;
    const unsigned qmask = 0xFu << (lane & 28);

    float acc[8];
#pragma unroll
    for (int c = 0; c < 8; c++) acc[c] = 0.0f;

    for (int k = qg; k < m; k += 32) {
        int w = (k >= o1) + (k >= o2) + (k >= o3);
        int e = slist[w * 512 + k - soff[w]];
        int j = e & 4095;
        float pw = (e & 4096) ? w12 : inv2;
        float2 y = xc2[j];

        // layer 1: this lane's 8 channels
        float h[8];
#pragma unroll
        for (int c = 0; c < 8; c++) {
            float s = sb1[cbase + c];
            s = fmaf(y.x,  sW1[cbase + c],      s);
            s = fmaf(y.y,  sW1[32 + cbase + c], s);
            s = fmaf(xq.x, sW1[64 + cbase + c], s);
            s = fmaf(xq.y, sW1[96 + cbase + c], s);
            h[c] = gelu_f(s);
        }
        // layer 2: gather h across quad via shfl, accumulate 8 channels
        float s2[8];
#pragma unroll
        for (int c = 0; c < 8; c++) s2[c] = sb2[cbase + c];
#pragma unroll
        for (int kk = 0; kk < 32; kk++) {
            float hv = __shfl_sync(qmask, h[kk & 7], kk >> 3, 4);
            const float* wrow = sW2 + kk * 32 + cbase;
#pragma unroll
            for (int c = 0; c < 8; c++) s2[c] = fmaf(hv, wrow[c], s2[c]);
        }
        float g[8];
#pragma unroll
        for (int c = 0; c < 8; c++) g[c] = gelu_f(s2[c]);

        // layer 3: gather g across quad, then weighted accumulation with f
        float s3[8];
#pragma unroll
        for (int c = 0; c < 8; c++) s3[c] = sb3[cbase + c];
#pragma unroll
        for (int kk = 0; kk < 32; kk++) {
            float gv = __shfl_sync(qmask, g[kk & 7], kk >> 3, 4);
            const float* wrow = sW3 + kk * 32 + cbase;
#pragma unroll
            for (int c = 0; c < 8; c++) s3[c] = fmaf(gv, wrow[c], s3[c]);
        }
        const float4* fj4 = (const float4*)(g_f + ((size_t)(b * NPT + j)) * 32 + cbase);
        float4 t0 = fj4[0];
        float4 t1 = fj4[1];
        acc[0] = fmaf(s3[0], t0.x * pw, acc[0]);
        acc[1] = fmaf(s3[1], t0.y * pw, acc[1]);
        acc[2] = fmaf(s3[2], t0.z * pw, acc[2]);
        acc[3] = fmaf(s3[3], t0.w * pw, acc[3]);
        acc[4] = fmaf(s3[4], t1.x * pw, acc[4]);
        acc[5] = fmaf(s3[5], t1.y * pw, acc[5]);
        acc[6] = fmaf(s3[6], t1.z * pw, acc[6]);
        acc[7] = fmaf(s3[7], t1.w * pw, acc[7]);
    }

#pragma unroll
    for (int c = 0; c < 8; c++) sacc[tid][c] = acc[c];
    __syncthreads();

    // ---- deterministic reduction over the 32 quads ----
    if (tid < 32) {
        int c3 = tid >> 3;        // channel group
        int r  = tid & 7;         // channel within group
        float v = 0.0f;
#pragma unroll
        for (int q = 0; q < 32; q++) v += sacc[q * 4 + c3][r];
        out[bi * 32 + tid] = v;
    }
}

extern "C" void kernel_launch(void* const* d_in, const int* in_sizes, int n_in,
                              void* d_out, int out_size) {
    const float* x_coord = (const float*)d_in[0];
    const float* pndata  = (const float*)d_in[1];
    const float* ltc     = (const float*)d_in[2];
    const float* W_lift  = (const float*)d_in[3];
    const float* b_lift  = (const float*)d_in[4];
    const float* kW1     = (const float*)d_in[5];
    const float* kb1     = (const float*)d_in[6];
    const float* kW2     = (const float*)d_in[7];
    const float* kb2     = (const float*)d_in[8];
    const float* kW3     = (const float*)d_in[9];
    const float* kb3     = (const float*)d_in[10];
    float* out = (float*)d_out;

    lift_kernel<<<(NB * NPT * CCH + 255) / 256, 256>>>(pndata, W_lift, b_lift);
    agg_kernel<<<NB * NLAT, 128>>>(x_coord, ltc, kW1, kb1, kW2, kb2, kW3, kb3, out);
}

// round 4
// speedup vs baseline: 1.1944x; 1.1944x over previous
#include <cuda_runtime.h>
#include <cuda_bf16.h>

#define NB   2
#define NPT  2048
#define NLAT 512
#define CCH  32
#define INC  16

// scratch for lifted features f[b, n, c]
__device__ float g_f[NB * NPT * CCH];

// jax.nn.gelu(approximate=True) == x * sigmoid(2*sqrt(2/pi)*(x + 0.044715 x^3))
__device__ __forceinline__ float gelu_f(float x) {
    float x3 = x * x * x;
    float z = 1.5957691216057308f * fmaf(0.044715f, x3, x);
    return x / (1.0f + __expf(-z));
}

__global__ void lift_kernel(const float* __restrict__ pndata,
                            const float* __restrict__ W,
                            const float* __restrict__ bias) {
    int idx = blockIdx.x * blockDim.x + threadIdx.x;
    if (idx >= NB * NPT * CCH) return;
    int c = idx & 31;
    int row = idx >> 5;
    const float* p = pndata + row * INC;
    float s = bias[c];
#pragma unroll
    for (int k = 0; k < INC; k++) s = fmaf(p[k], W[k * CCH + c], s);
    g_f[idx] = s;
}

__global__ void __launch_bounds__(128) agg_kernel(
    const float* __restrict__ x_coord,
    const float* __restrict__ ltc,
    const float* __restrict__ kW1, const float* __restrict__ kb1,
    const float* __restrict__ kW2, const float* __restrict__ kb2,
    const float* __restrict__ kW3, const float* __restrict__ kb3,
    float* __restrict__ out)
{
    __shared__ float sW1[128], sb1[32], sW2[1024], sb2[32], sW3[1024], sb3[32];
    __shared__ int   slist[NPT];           // per-warp segmented compact list
    __shared__ int   swcnt[4], swcnt1[4], soff[5];
    __shared__ float swred[4][32];

    const int tid  = threadIdx.x;
    const int wid  = tid >> 5;
    const int lane = tid & 31;
    const int bi   = blockIdx.x;           // = b*NLAT + i
    const int b    = bi >> 9;
    const int i    = bi & (NLAT - 1);

    // load weights to shared
    sW1[tid] = kW1[tid];
    for (int t = tid; t < 1024; t += 128) { sW2[t] = kW2[t]; sW3[t] = kW3[t]; }
    if (tid < 32) { sb1[tid] = kb1[tid]; sb2[tid] = kb2[tid]; sb3[tid] = kb3[tid]; }

    const float2 xq = ((const float2*)ltc)[i];
    const float R1SQ = (float)(0.07 * 0.07);   // matches jax f32(double) constants
    const float R2SQ = (float)(0.14 * 0.14);

    // ---- Phase A: deterministic ballot compaction, per-warp j segments ----
    const float2* xc2 = (const float2*)x_coord + (size_t)b * NPT;
    const int wbase = wid * 512;
    int wcount = 0, wcount1 = 0;
    for (int jj = lane; jj < 512; jj += 32) {
        int j = wbase + jj;
        float2 y = xc2[j];
        float d0 = y.x - xq.x;
        float d1 = y.y - xq.y;
        // exact match to jax: d0*d0 + d1*d1 with NO fma contraction
        float d2 = __fadd_rn(__fmul_rn(d0, d0), __fmul_rn(d1, d1));
        bool sel = (d2 <= R2SQ);
        bool in1 = (d2 <= R1SQ);
        unsigned bal = __ballot_sync(0xffffffffu, sel);
        if (sel) {
            int pos = wcount + __popc(bal & ((1u << lane) - 1u));
            slist[wbase + pos] = j | ((int)in1 << 12);
        }
        wcount  += __popc(bal);
        wcount1 += __popc(__ballot_sync(0xffffffffu, in1));
    }
    if (lane == 0) { swcnt[wid] = wcount; swcnt1[wid] = wcount1; }
    __syncthreads();
    if (tid == 0) {
        int o = 0;
#pragma unroll
        for (int w = 0; w < 4; w++) { soff[w] = o; o += swcnt[w]; }
        soff[4] = o;
        swcnt1[0] = swcnt1[0] + swcnt1[1] + swcnt1[2] + swcnt1[3];
    }
    __syncthreads();

    const int   m    = soff[4];
    const int   c1   = swcnt1[0];
    const float inv2 = 1.0f / fmaxf((float)m,  1.0f);
    const float inv1 = 1.0f / fmaxf((float)c1, 1.0f);
    const float w12  = inv1 + inv2;
    const int o1 = soff[1], o2 = soff[2], o3 = soff[3];

    // ---- Phase B: quad handles 2 pairs/iter; lane owns 8 of 32 channels ----
    const int      qg    = tid >> 2;                 // quad id (0..31)
    const int      qid   = tid & 3;                  // channel group
    const int      cbase = qid * 8;
    const unsigned qmask = 0xFu << (lane & 28);

    // pair-invariant part of layer 1: b1 + xq @ W1[2:4]
    float hbase[8];
#pragma unroll
    for (int c = 0; c < 8; c++)
        hbase[c] = fmaf(xq.x, sW1[64 + cbase + c],
                   fmaf(xq.y, sW1[96 + cbase + c], sb1[cbase + c]));

    float acc[8];
#pragma unroll
    for (int c = 0; c < 8; c++) acc[c] = 0.0f;

    for (int k = qg * 2; k < m; k += 64) {
        int w0 = (k >= o1) + (k >= o2) + (k >= o3);
        int e0 = slist[w0 * 512 + k - soff[w0]];
        int k1 = k + 1;
        bool has1 = (k1 < m);
        int kc = has1 ? k1 : k;
        int w1 = (kc >= o1) + (kc >= o2) + (kc >= o3);
        int e1 = slist[w1 * 512 + kc - soff[w1]];
        int j0 = e0 & 4095, j1 = e1 & 4095;
        float pw0 = (e0 & 4096) ? w12 : inv2;
        float pw1 = has1 ? ((e1 & 4096) ? w12 : inv2) : 0.0f;
        float2 y0 = xc2[j0];
        float2 y1 = xc2[j1];

        // layer 1 (2 FMA + gelu per channel per pair)
        float h0[8], h1[8];
#pragma unroll
        for (int c = 0; c < 8; c++) {
            float wa = sW1[cbase + c];
            float wb = sW1[32 + cbase + c];
            h0[c] = gelu_f(fmaf(y0.x, wa, fmaf(y0.y, wb, hbase[c])));
            h1[c] = gelu_f(fmaf(y1.x, wa, fmaf(y1.y, wb, hbase[c])));
        }

        // layer 2: weight row loaded once, used by both pairs
        float s20[8], s21[8];
#pragma unroll
        for (int c = 0; c < 8; c++) { s20[c] = sb2[cbase + c]; s21[c] = s20[c]; }
#pragma unroll
        for (int kk = 0; kk < 32; kk++) {
            const float4* w4 = (const float4*)(sW2 + kk * 32 + cbase);
            float4 wa = w4[0];
            float4 wb = w4[1];
            float hv0 = __shfl_sync(qmask, h0[kk & 7], kk >> 3, 4);
            float hv1 = __shfl_sync(qmask, h1[kk & 7], kk >> 3, 4);
            s20[0] = fmaf(hv0, wa.x, s20[0]);  s21[0] = fmaf(hv1, wa.x, s21[0]);
            s20[1] = fmaf(hv0, wa.y, s20[1]);  s21[1] = fmaf(hv1, wa.y, s21[1]);
            s20[2] = fmaf(hv0, wa.z, s20[2]);  s21[2] = fmaf(hv1, wa.z, s21[2]);
            s20[3] = fmaf(hv0, wa.w, s20[3]);  s21[3] = fmaf(hv1, wa.w, s21[3]);
            s20[4] = fmaf(hv0, wb.x, s20[4]);  s21[4] = fmaf(hv1, wb.x, s21[4]);
            s20[5] = fmaf(hv0, wb.y, s20[5]);  s21[5] = fmaf(hv1, wb.y, s21[5]);
            s20[6] = fmaf(hv0, wb.z, s20[6]);  s21[6] = fmaf(hv1, wb.z, s21[6]);
            s20[7] = fmaf(hv0, wb.w, s20[7]);  s21[7] = fmaf(hv1, wb.w, s21[7]);
        }
#pragma unroll
        for (int c = 0; c < 8; c++) { s20[c] = gelu_f(s20[c]); s21[c] = gelu_f(s21[c]); }

        // layer 3 (h0/h1 dead; s20/s21 now hold g)
        float s30[8], s31[8];
#pragma unroll
        for (int c = 0; c < 8; c++) { s30[c] = sb3[cbase + c]; s31[c] = s30[c]; }
#pragma unroll
        for (int kk = 0; kk < 32; kk++) {
            const float4* w4 = (const float4*)(sW3 + kk * 32 + cbase);
            float4 wa = w4[0];
            float4 wb = w4[1];
            float gv0 = __shfl_sync(qmask, s20[kk & 7], kk >> 3, 4);
            float gv1 = __shfl_sync(qmask, s21[kk & 7], kk >> 3, 4);
            s30[0] = fmaf(gv0, wa.x, s30[0]);  s31[0] = fmaf(gv1, wa.x, s31[0]);
            s30[1] = fmaf(gv0, wa.y, s30[1]);  s31[1] = fmaf(gv1, wa.y, s31[1]);
            s30[2] = fmaf(gv0, wa.z, s30[2]);  s31[2] = fmaf(gv1, wa.z, s31[2]);
            s30[3] = fmaf(gv0, wa.w, s30[3]);  s31[3] = fmaf(gv1, wa.w, s31[3]);
            s30[4] = fmaf(gv0, wb.x, s30[4]);  s31[4] = fmaf(gv1, wb.x, s31[4]);
            s30[5] = fmaf(gv0, wb.y, s30[5]);  s31[5] = fmaf(gv1, wb.y, s31[5]);
            s30[6] = fmaf(gv0, wb.z, s30[6]);  s31[6] = fmaf(gv1, wb.z, s31[6]);
            s30[7] = fmaf(gv0, wb.w, s30[7]);  s31[7] = fmaf(gv1, wb.w, s31[7]);
        }

        // weighted accumulation with lifted features
        const float4* f0 = (const float4*)(g_f + ((size_t)(b * NPT + j0)) * 32 + cbase);
        const float4* f1 = (const float4*)(g_f + ((size_t)(b * NPT + j1)) * 32 + cbase);
        float4 a0 = f0[0], b0 = f0[1];
        float4 a1 = f1[0], b1v = f1[1];
        acc[0] = fmaf(s30[0], a0.x * pw0, acc[0]);  acc[0] = fmaf(s31[0], a1.x * pw1, acc[0]);
        acc[1] = fmaf(s30[1], a0.y * pw0, acc[1]);  acc[1] = fmaf(s31[1], a1.y * pw1, acc[1]);
        acc[2] = fmaf(s30[2], a0.z * pw0, acc[2]);  acc[2] = fmaf(s31[2], a1.z * pw1, acc[2]);
        acc[3] = fmaf(s30[3], a0.w * pw0, acc[3]);  acc[3] = fmaf(s31[3], a1.w * pw1, acc[3]);
        acc[4] = fmaf(s30[4], b0.x * pw0, acc[4]);  acc[4] = fmaf(s31[4], b1v.x * pw1, acc[4]);
        acc[5] = fmaf(s30[5], b0.y * pw0, acc[5]);  acc[5] = fmaf(s31[5], b1v.y * pw1, acc[5]);
        acc[6] = fmaf(s30[6], b0.z * pw0, acc[6]);  acc[6] = fmaf(s31[6], b1v.z * pw1, acc[6]);
        acc[7] = fmaf(s30[7], b0.w * pw0, acc[7]);  acc[7] = fmaf(s31[7], b1v.w * pw1, acc[7]);
    }

    // ---- deterministic reduction: butterfly over the 8 quads in each warp ----
#pragma unroll
    for (int c = 0; c < 8; c++) {
        float v = acc[c];
        v += __shfl_xor_sync(0xffffffffu, v, 4);
        v += __shfl_xor_sync(0xffffffffu, v, 8);
        v += __shfl_xor_sync(0xffffffffu, v, 16);
        if (lane < 4) swred[wid][cbase + c] = v;
    }
    __syncthreads();
    if (tid < 32)
        out[bi * 32 + tid] = (swred[0][tid] + swred[1][tid]) + (swred[2][tid] + swred[3][tid]);
}

extern "C" void kernel_launch(void* const* d_in, const int* in_sizes, int n_in,
                              void* d_out, int out_size) {
    const float* x_coord = (const float*)d_in[0];
    const float* pndata  = (const float*)d_in[1];
    const float* ltc     = (const float*)d_in[2];
    const float* W_lift  = (const float*)d_in[3];
    const float* b_lift  = (const float*)d_in[4];
    const float* kW1     = (const float*)d_in[5];
    const float* kb1     = (const float*)d_in[6];
    const float* kW2     = (const float*)d_in[7];
    const float* kb2     = (const float*)d_in[8];
    const float* kW3     = (const float*)d_in[9];
    const float* kb3     = (const float*)d_in[10];
    float* out = (float*)d_out;

    lift_kernel<<<(NB * NPT * CCH + 255) / 256, 256>>>(pndata, W_lift, b_lift);
    agg_kernel<<<NB * NLAT, 128>>>(x_coord, ltc, kW1, kb1, kW2, kb2, kW3, kb3, out);
}

// round 5
// speedup vs baseline: 1.2411x; 1.0391x over previous
#include <cuda_runtime.h>
#include <cuda_bf16.h>

#define NB   2
#define NPT  2048
#define NLAT 512
#define CCH  32
#define INC  16

typedef unsigned long long u64;

// scratch for lifted features f[b, n, c]
__device__ float g_f[NB * NPT * CCH];

// ---- f32x2 packed helpers (sm_103a) ----
__device__ __forceinline__ u64 pk2(float lo, float hi) {
    u64 r; asm("mov.b64 %0, {%1, %2};" : "=l"(r) : "f"(lo), "f"(hi)); return r;
}
__device__ __forceinline__ void upk2(u64 v, float& lo, float& hi) {
    asm("mov.b64 {%0, %1}, %2;" : "=f"(lo), "=f"(hi) : "l"(v));
}
__device__ __forceinline__ u64 ffma2(u64 a, u64 b, u64 c) {
    u64 d; asm("fma.rn.f32x2 %0, %1, %2, %3;" : "=l"(d) : "l"(a), "l"(b), "l"(c)); return d;
}
__device__ __forceinline__ u64 fmul2(u64 a, u64 b) {
    u64 d; asm("mul.rn.f32x2 %0, %1, %2;" : "=l"(d) : "l"(a), "l"(b)); return d;
}

// gelu(x) = 0.5*x*(1 + tanh(0.7978845608*(x + 0.044715*x^3)))  (tanh MUFU, no div)
__device__ __forceinline__ float gelu_f(float x) {
    float x3 = x * x * x;
    float z = 0.7978845608028654f * fmaf(0.044715f, x3, x);
    float t; asm("tanh.approx.f32 %0, %1;" : "=f"(t) : "f"(z));
    float hx = 0.5f * x;
    return fmaf(hx, t, hx);
}

__global__ void lift_kernel(const float* __restrict__ pndata,
                            const float* __restrict__ W,
                            const float* __restrict__ bias) {
    int idx = blockIdx.x * blockDim.x + threadIdx.x;
    if (idx >= NB * NPT * CCH) return;
    int c = idx & 31;
    int row = idx >> 5;
    const float* p = pndata + row * INC;
    float s = bias[c];
#pragma unroll
    for (int k = 0; k < INC; k++) s = fmaf(p[k], W[k * CCH + c], s);
    g_f[idx] = s;
}

__global__ void __launch_bounds__(128) agg_kernel(
    const float* __restrict__ x_coord,
    const float* __restrict__ ltc,
    const float* __restrict__ kW1, const float* __restrict__ kb1,
    const float* __restrict__ kW2, const float* __restrict__ kb2,
    const float* __restrict__ kW3, const float* __restrict__ kb3,
    float* __restrict__ out)
{
    __shared__ float sW1[128], sb1[32], sW2[1024], sb2[32], sW3[1024], sb3[32];
    __shared__ int   slist[NPT];           // per-warp segmented compact list
    __shared__ int   swcnt[4], swcnt1[4], soff[5];
    __shared__ float swred[4][32];

    const int tid  = threadIdx.x;
    const int wid  = tid >> 5;
    const int lane = tid & 31;
    const int bi   = blockIdx.x;           // = b*NLAT + i
    const int b    = bi >> 9;
    const int i    = bi & (NLAT - 1);

    // load weights to shared
    sW1[tid] = kW1[tid];
    for (int t = tid; t < 1024; t += 128) { sW2[t] = kW2[t]; sW3[t] = kW3[t]; }
    if (tid < 32) { sb1[tid] = kb1[tid]; sb2[tid] = kb2[tid]; sb3[tid] = kb3[tid]; }

    const float2 xq = ((const float2*)ltc)[i];
    const float R1SQ = (float)(0.07 * 0.07);   // matches jax f32(double) constants
    const float R2SQ = (float)(0.14 * 0.14);

    // ---- Phase A: deterministic ballot compaction, per-warp j segments ----
    const float2* xc2 = (const float2*)x_coord + (size_t)b * NPT;
    const int wbase = wid * 512;
    int wcount = 0, wcount1 = 0;
    for (int jj = lane; jj < 512; jj += 32) {
        int j = wbase + jj;
        float2 y = xc2[j];
        float d0 = y.x - xq.x;
        float d1 = y.y - xq.y;
        // exact match to jax: d0*d0 + d1*d1 with NO fma contraction
        float d2 = __fadd_rn(__fmul_rn(d0, d0), __fmul_rn(d1, d1));
        bool sel = (d2 <= R2SQ);
        bool in1 = (d2 <= R1SQ);
        unsigned bal = __ballot_sync(0xffffffffu, sel);
        if (sel) {
            int pos = wcount + __popc(bal & ((1u << lane) - 1u));
            slist[wbase + pos] = j | ((int)in1 << 12);
        }
        wcount  += __popc(bal);
        wcount1 += __popc(__ballot_sync(0xffffffffu, in1));
    }
    if (lane == 0) { swcnt[wid] = wcount; swcnt1[wid] = wcount1; }
    __syncthreads();
    if (tid == 0) {
        int o = 0;
#pragma unroll
        for (int w = 0; w < 4; w++) { soff[w] = o; o += swcnt[w]; }
        soff[4] = o;
        swcnt1[0] = swcnt1[0] + swcnt1[1] + swcnt1[2] + swcnt1[3];
    }
    __syncthreads();

    const int   m    = soff[4];
    const int   c1   = swcnt1[0];
    const float inv2 = 1.0f / fmaxf((float)m,  1.0f);
    const float inv1 = 1.0f / fmaxf((float)c1, 1.0f);
    const float w12  = inv1 + inv2;
    const int o1 = soff[1], o2 = soff[2], o3 = soff[3];

    // ---- Phase B: quad handles 2 pairs/iter; lane owns 8 channels (4 f32x2) ----
    const int      qg    = tid >> 2;                 // quad id (0..31)
    const int      qid   = tid & 3;                  // channel group
    const int      cbase = qid * 8;
    const unsigned qmask = 0xFu << (lane & 28);

    // packed views of this lane's channel columns
    const u64* w1r0 = (const u64*)(sW1 + cbase);
    const u64* w1r1 = (const u64*)(sW1 + 32 + cbase);
    const float* sW2cb = sW2 + cbase;
    const float* sW3cb = sW3 + cbase;

    // pair-invariant part of layer 1: b1 + xq @ W1[2:4]  (packed)
    u64 hbp[4];
    {
        const u64* w1r2 = (const u64*)(sW1 + 64 + cbase);
        const u64* w1r3 = (const u64*)(sW1 + 96 + cbase);
        const u64* b1p  = (const u64*)(sb1 + cbase);
        u64 xqx = pk2(xq.x, xq.x), xqy = pk2(xq.y, xq.y);
#pragma unroll
        for (int q = 0; q < 4; q++)
            hbp[q] = ffma2(xqx, w1r2[q], ffma2(xqy, w1r3[q], b1p[q]));
    }
    u64 b2p[4], b3p[4];
#pragma unroll
    for (int q = 0; q < 4; q++) {
        b2p[q] = ((const u64*)(sb2 + cbase))[q];
        b3p[q] = ((const u64*)(sb3 + cbase))[q];
    }

    u64 accp[4];
#pragma unroll
    for (int q = 0; q < 4; q++) accp[q] = pk2(0.0f, 0.0f);

    for (int k = qg * 2; k < m; k += 64) {
        int w0 = (k >= o1) + (k >= o2) + (k >= o3);
        int e0 = slist[w0 * 512 + k - soff[w0]];
        int k1 = k + 1;
        bool has1 = (k1 < m);
        int kc = has1 ? k1 : k;
        int w1 = (kc >= o1) + (kc >= o2) + (kc >= o3);
        int e1 = slist[w1 * 512 + kc - soff[w1]];
        int j0 = e0 & 4095, j1 = e1 & 4095;
        float pw0 = (e0 & 4096) ? w12 : inv2;
        float pw1 = has1 ? ((e1 & 4096) ? w12 : inv2) : 0.0f;
        float2 y0 = xc2[j0];
        float2 y1 = xc2[j1];

        // layer 1 (packed pre-activation, scalar gelu)
        float h0[8], h1[8];
        {
            u64 y0x = pk2(y0.x, y0.x), y0y = pk2(y0.y, y0.y);
            u64 y1x = pk2(y1.x, y1.x), y1y = pk2(y1.y, y1.y);
#pragma unroll
            for (int q = 0; q < 4; q++) {
                u64 s0 = ffma2(y0x, w1r0[q], ffma2(y0y, w1r1[q], hbp[q]));
                u64 s1 = ffma2(y1x, w1r0[q], ffma2(y1y, w1r1[q], hbp[q]));
                float a, bb;
                upk2(s0, a, bb); h0[2*q] = gelu_f(a); h0[2*q+1] = gelu_f(bb);
                upk2(s1, a, bb); h1[2*q] = gelu_f(a); h1[2*q+1] = gelu_f(bb);
            }
        }

        // layer 2: packed channel-pairs; weight row LDS shared across both pairs
        u64 s20[4], s21[4];
#pragma unroll
        for (int q = 0; q < 4; q++) { s20[q] = b2p[q]; s21[q] = b2p[q]; }
#pragma unroll
        for (int kk = 0; kk < 32; kk++) {
            const ulonglong2* w4 = (const ulonglong2*)(sW2cb + kk * 32);
            ulonglong2 wa = w4[0];     // ch 0-3 (2x f32x2)
            ulonglong2 wb = w4[1];     // ch 4-7
            float hv0 = __shfl_sync(qmask, h0[kk & 7], kk >> 3, 4);
            float hv1 = __shfl_sync(qmask, h1[kk & 7], kk >> 3, 4);
            u64 hp0 = pk2(hv0, hv0);
            u64 hp1 = pk2(hv1, hv1);
            s20[0] = ffma2(hp0, wa.x, s20[0]);  s21[0] = ffma2(hp1, wa.x, s21[0]);
            s20[1] = ffma2(hp0, wa.y, s20[1]);  s21[1] = ffma2(hp1, wa.y, s21[1]);
            s20[2] = ffma2(hp0, wb.x, s20[2]);  s21[2] = ffma2(hp1, wb.x, s21[2]);
            s20[3] = ffma2(hp0, wb.y, s20[3]);  s21[3] = ffma2(hp1, wb.y, s21[3]);
        }
        float g0[8], g1[8];
#pragma unroll
        for (int q = 0; q < 4; q++) {
            float a, bb;
            upk2(s20[q], a, bb); g0[2*q] = gelu_f(a); g0[2*q+1] = gelu_f(bb);
            upk2(s21[q], a, bb); g1[2*q] = gelu_f(a); g1[2*q+1] = gelu_f(bb);
        }

        // layer 3: packed
        u64 s30[4], s31[4];
#pragma unroll
        for (int q = 0; q < 4; q++) { s30[q] = b3p[q]; s31[q] = b3p[q]; }
#pragma unroll
        for (int kk = 0; kk < 32; kk++) {
            const ulonglong2* w4 = (const ulonglong2*)(sW3cb + kk * 32);
            ulonglong2 wa = w4[0];
            ulonglong2 wb = w4[1];
            float gv0 = __shfl_sync(qmask, g0[kk & 7], kk >> 3, 4);
            float gv1 = __shfl_sync(qmask, g1[kk & 7], kk >> 3, 4);
            u64 gp0 = pk2(gv0, gv0);
            u64 gp1 = pk2(gv1, gv1);
            s30[0] = ffma2(gp0, wa.x, s30[0]);  s31[0] = ffma2(gp1, wa.x, s31[0]);
            s30[1] = ffma2(gp0, wa.y, s30[1]);  s31[1] = ffma2(gp1, wa.y, s31[1]);
            s30[2] = ffma2(gp0, wb.x, s30[2]);  s31[2] = ffma2(gp1, wb.x, s31[2]);
            s30[3] = ffma2(gp0, wb.y, s30[3]);  s31[3] = ffma2(gp1, wb.y, s31[3]);
        }

        // weighted accumulation with lifted features (packed)
        const ulonglong2* f0 = (const ulonglong2*)(g_f + ((size_t)(b * NPT + j0)) * 32 + cbase);
        const ulonglong2* f1 = (const ulonglong2*)(g_f + ((size_t)(b * NPT + j1)) * 32 + cbase);
        ulonglong2 fa0 = f0[0], fb0 = f0[1];
        ulonglong2 fa1 = f1[0], fb1 = f1[1];
        u64 pw0p = pk2(pw0, pw0), pw1p = pk2(pw1, pw1);
        accp[0] = ffma2(s30[0], fmul2(fa0.x, pw0p), accp[0]);
        accp[1] = ffma2(s30[1], fmul2(fa0.y, pw0p), accp[1]);
        accp[2] = ffma2(s30[2], fmul2(fb0.x, pw0p), accp[2]);
        accp[3] = ffma2(s30[3], fmul2(fb0.y, pw0p), accp[3]);
        accp[0] = ffma2(s31[0], fmul2(fa1.x, pw1p), accp[0]);
        accp[1] = ffma2(s31[1], fmul2(fa1.y, pw1p), accp[1]);
        accp[2] = ffma2(s31[2], fmul2(fb1.x, pw1p), accp[2]);
        accp[3] = ffma2(s31[3], fmul2(fb1.y, pw1p), accp[3]);
    }

    // ---- deterministic reduction: butterfly over the 8 quads in each warp ----
    float acc[8];
#pragma unroll
    for (int q = 0; q < 4; q++) upk2(accp[q], acc[2*q], acc[2*q+1]);
#pragma unroll
    for (int c = 0; c < 8; c++) {
        float v = acc[c];
        v += __shfl_xor_sync(0xffffffffu, v, 4);
        v += __shfl_xor_sync(0xffffffffu, v, 8);
        v += __shfl_xor_sync(0xffffffffu, v, 16);
        if (lane < 4) swred[wid][cbase + c] = v;
    }
    __syncthreads();
    if (tid < 32)
        out[bi * 32 + tid] = (swred[0][tid] + swred[1][tid]) + (swred[2][tid] + swred[3][tid]);
}

extern "C" void kernel_launch(void* const* d_in, const int* in_sizes, int n_in,
                              void* d_out, int out_size) {
    const float* x_coord = (const float*)d_in[0];
    const float* pndata  = (const float*)d_in[1];
    const float* ltc     = (const float*)d_in[2];
    const float* W_lift  = (const float*)d_in[3];
    const float* b_lift  = (const float*)d_in[4];
    const float* kW1     = (const float*)d_in[5];
    const float* kb1     = (const float*)d_in[6];
    const float* kW2     = (const float*)d_in[7];
    const float* kb2     = (const float*)d_in[8];
    const float* kW3     = (const float*)d_in[9];
    const float* kb3     = (const float*)d_in[10];
    float* out = (float*)d_out;

    lift_kernel<<<(NB * NPT * CCH + 255) / 256, 256>>>(pndata, W_lift, b_lift);
    agg_kernel<<<NB * NLAT, 128>>>(x_coord, ltc, kW1, kb1, kW2, kb2, kW3, kb3, out);
}

// round 6
// speedup vs baseline: 1.3630x; 1.0982x over previous
#include <cuda_runtime.h>
#include <cuda_bf16.h>

#define NB   2
#define NPT  2048
#define NLAT 512
#define CCH  32
#define INC  16

typedef unsigned long long u64;

// scratch for lifted features f[b, n, c]
__device__ float g_f[NB * NPT * CCH];

// ---- f32x2 packed helpers (sm_103a) ----
__device__ __forceinline__ u64 pk2(float lo, float hi) {
    u64 r; asm("mov.b64 %0, {%1, %2};" : "=l"(r) : "f"(lo), "f"(hi)); return r;
}
__device__ __forceinline__ void upk2(u64 v, float& lo, float& hi) {
    asm("mov.b64 {%0, %1}, %2;" : "=f"(lo), "=f"(hi) : "l"(v));
}
__device__ __forceinline__ u64 ffma2(u64 a, u64 b, u64 c) {
    u64 d; asm("fma.rn.f32x2 %0, %1, %2, %3;" : "=l"(d) : "l"(a), "l"(b), "l"(c)); return d;
}
__device__ __forceinline__ u64 fmul2(u64 a, u64 b) {
    u64 d; asm("mul.rn.f32x2 %0, %1, %2;" : "=l"(d) : "l"(a), "l"(b)); return d;
}

// gelu(x) = 0.5*x*(1 + tanh(0.7978845608*(x + 0.044715*x^3)))  (tanh MUFU, no div)
__device__ __forceinline__ float gelu_f(float x) {
    float x3 = x * x * x;
    float z = 0.7978845608028654f * fmaf(0.044715f, x3, x);
    float t; asm("tanh.approx.f32 %0, %1;" : "=f"(t) : "f"(z));
    float hx = 0.5f * x;
    return fmaf(hx, t, hx);
}

__global__ void lift_kernel(const float* __restrict__ pndata,
                            const float* __restrict__ W,
                            const float* __restrict__ bias) {
    int idx = blockIdx.x * blockDim.x + threadIdx.x;
    if (idx >= NB * NPT * CCH) return;
    int c = idx & 31;
    int row = idx >> 5;
    const float* p = pndata + row * INC;
    float s = bias[c];
#pragma unroll
    for (int k = 0; k < INC; k++) s = fmaf(p[k], W[k * CCH + c], s);
    g_f[idx] = s;
}

__global__ void __launch_bounds__(64) agg_kernel(
    const float* __restrict__ x_coord,
    const float* __restrict__ ltc,
    const float* __restrict__ kW1, const float* __restrict__ kb1,
    const float* __restrict__ kW2, const float* __restrict__ kb2,
    const float* __restrict__ kW3, const float* __restrict__ kb3,
    float* __restrict__ out)
{
    __shared__ float sW1[128], sb1[32], sW2[1024], sb2[32], sW3[1024], sb3[32];
    __shared__ unsigned short slist[NPT];  // j | (in1<<15), per-warp segments
    __shared__ int   swcnt[2], swcnt1[2], soff[3];
    __shared__ float swred[2][32];

    const int tid  = threadIdx.x;
    const int wid  = tid >> 5;
    const int lane = tid & 31;
    const int bi   = blockIdx.x;           // = b*NLAT + i
    const int b    = bi >> 9;
    const int i    = bi & (NLAT - 1);

    // load weights to shared (64 threads)
    for (int t = tid; t < 128; t += 64) sW1[t] = kW1[t];
    for (int t = tid; t < 1024; t += 64) { sW2[t] = kW2[t]; sW3[t] = kW3[t]; }
    if (tid < 32) { sb1[tid] = kb1[tid]; sb2[tid] = kb2[tid]; sb3[tid] = kb3[tid]; }

    const float2 xq = ((const float2*)ltc)[i];
    const float R1SQ = (float)(0.07 * 0.07);   // matches jax f32(double) constants
    const float R2SQ = (float)(0.14 * 0.14);

    // ---- Phase A: deterministic ballot compaction, 2 warp segments of 1024 ----
    const float2* xc2 = (const float2*)x_coord + (size_t)b * NPT;
    const int wbase = wid * 1024;
    int wcount = 0, wcount1 = 0;
    for (int jj = lane; jj < 1024; jj += 32) {
        int j = wbase + jj;
        float2 y = xc2[j];
        float d0 = y.x - xq.x;
        float d1 = y.y - xq.y;
        // exact match to jax: d0*d0 + d1*d1 with NO fma contraction
        float d2 = __fadd_rn(__fmul_rn(d0, d0), __fmul_rn(d1, d1));
        bool sel = (d2 <= R2SQ);
        bool in1 = (d2 <= R1SQ);
        unsigned bal = __ballot_sync(0xffffffffu, sel);
        if (sel) {
            int pos = wcount + __popc(bal & ((1u << lane) - 1u));
            slist[wbase + pos] = (unsigned short)(j | ((int)in1 << 15));
        }
        wcount  += __popc(bal);
        wcount1 += __popc(__ballot_sync(0xffffffffu, in1));
    }
    if (lane == 0) { swcnt[wid] = wcount; swcnt1[wid] = wcount1; }
    __syncthreads();
    if (tid == 0) {
        soff[0] = 0;
        soff[1] = swcnt[0];
        soff[2] = swcnt[0] + swcnt[1];
        swcnt1[0] = swcnt1[0] + swcnt1[1];
    }
    __syncthreads();

    const int   m    = soff[2];
    const int   c1   = swcnt1[0];
    const float inv2 = 1.0f / fmaxf((float)m,  1.0f);
    const float inv1 = 1.0f / fmaxf((float)c1, 1.0f);
    const float w12  = inv1 + inv2;
    const int o1 = soff[1];

    // ---- Phase B: quad handles 2 pairs/iter; lane owns 8 channels (4 f32x2) ----
    const int      qg    = tid >> 2;                 // quad id (0..15)
    const int      qid   = tid & 3;                  // channel group
    const int      cbase = qid * 8;
    const unsigned qmask = 0xFu << (lane & 28);

    // packed views of this lane's channel columns
    const u64* w1r0 = (const u64*)(sW1 + cbase);
    const u64* w1r1 = (const u64*)(sW1 + 32 + cbase);
    const float* sW2cb = sW2 + cbase;
    const float* sW3cb = sW3 + cbase;

    // pair-invariant part of layer 1: b1 + xq @ W1[2:4]  (packed)
    u64 hbp[4];
    {
        const u64* w1r2 = (const u64*)(sW1 + 64 + cbase);
        const u64* w1r3 = (const u64*)(sW1 + 96 + cbase);
        const u64* b1p  = (const u64*)(sb1 + cbase);
        u64 xqx = pk2(xq.x, xq.x), xqy = pk2(xq.y, xq.y);
#pragma unroll
        for (int q = 0; q < 4; q++)
            hbp[q] = ffma2(xqx, w1r2[q], ffma2(xqy, w1r3[q], b1p[q]));
    }
    u64 b2p[4], b3p[4];
#pragma unroll
    for (int q = 0; q < 4; q++) {
        b2p[q] = ((const u64*)(sb2 + cbase))[q];
        b3p[q] = ((const u64*)(sb3 + cbase))[q];
    }

    u64 accp[4];
#pragma unroll
    for (int q = 0; q < 4; q++) accp[q] = pk2(0.0f, 0.0f);

    for (int k = qg * 2; k < m; k += 32) {
        int w0 = (k >= o1) ? 1 : 0;
        int e0 = slist[w0 * 1024 + k - soff[w0]];
        int k1 = k + 1;
        bool has1 = (k1 < m);
        int kc = has1 ? k1 : k;
        int w1 = (kc >= o1) ? 1 : 0;
        int e1 = slist[w1 * 1024 + kc - soff[w1]];
        int j0 = e0 & 2047, j1 = e1 & 2047;
        float pw0 = (e0 & 32768) ? w12 : inv2;
        float pw1 = has1 ? ((e1 & 32768) ? w12 : inv2) : 0.0f;
        float2 y0 = xc2[j0];
        float2 y1 = xc2[j1];

        // layer 1 (packed pre-activation, scalar gelu)
        float h0[8], h1[8];
        {
            u64 y0x = pk2(y0.x, y0.x), y0y = pk2(y0.y, y0.y);
            u64 y1x = pk2(y1.x, y1.x), y1y = pk2(y1.y, y1.y);
#pragma unroll
            for (int q = 0; q < 4; q++) {
                u64 s0 = ffma2(y0x, w1r0[q], ffma2(y0y, w1r1[q], hbp[q]));
                u64 s1 = ffma2(y1x, w1r0[q], ffma2(y1y, w1r1[q], hbp[q]));
                float a, bb;
                upk2(s0, a, bb); h0[2*q] = gelu_f(a); h0[2*q+1] = gelu_f(bb);
                upk2(s1, a, bb); h1[2*q] = gelu_f(a); h1[2*q+1] = gelu_f(bb);
            }
        }

        // layer 2: packed channel-pairs; weight row LDS shared across both pairs
        u64 s20[4], s21[4];
#pragma unroll
        for (int q = 0; q < 4; q++) { s20[q] = b2p[q]; s21[q] = b2p[q]; }
#pragma unroll
        for (int kk = 0; kk < 32; kk++) {
            const ulonglong2* w4 = (const ulonglong2*)(sW2cb + kk * 32);
            ulonglong2 wa = w4[0];     // ch 0-3 (2x f32x2)
            ulonglong2 wb = w4[1];     // ch 4-7
            float hv0 = __shfl_sync(qmask, h0[kk & 7], kk >> 3, 4);
            float hv1 = __shfl_sync(qmask, h1[kk & 7], kk >> 3, 4);
            u64 hp0 = pk2(hv0, hv0);
            u64 hp1 = pk2(hv1, hv1);
            s20[0] = ffma2(hp0, wa.x, s20[0]);  s21[0] = ffma2(hp1, wa.x, s21[0]);
            s20[1] = ffma2(hp0, wa.y, s20[1]);  s21[1] = ffma2(hp1, wa.y, s21[1]);
            s20[2] = ffma2(hp0, wb.x, s20[2]);  s21[2] = ffma2(hp1, wb.x, s21[2]);
            s20[3] = ffma2(hp0, wb.y, s20[3]);  s21[3] = ffma2(hp1, wb.y, s21[3]);
        }
        float g0[8], g1[8];
#pragma unroll
        for (int q = 0; q < 4; q++) {
            float a, bb;
            upk2(s20[q], a, bb); g0[2*q] = gelu_f(a); g0[2*q+1] = gelu_f(bb);
            upk2(s21[q], a, bb); g1[2*q] = gelu_f(a); g1[2*q+1] = gelu_f(bb);
        }

        // layer 3: packed
        u64 s30[4], s31[4];
#pragma unroll
        for (int q = 0; q < 4; q++) { s30[q] = b3p[q]; s31[q] = b3p[q]; }
#pragma unroll
        for (int kk = 0; kk < 32; kk++) {
            const ulonglong2* w4 = (const ulonglong2*)(sW3cb + kk * 32);
            ulonglong2 wa = w4[0];
            ulonglong2 wb = w4[1];
            float gv0 = __shfl_sync(qmask, g0[kk & 7], kk >> 3, 4);
            float gv1 = __shfl_sync(qmask, g1[kk & 7], kk >> 3, 4);
            u64 gp0 = pk2(gv0, gv0);
            u64 gp1 = pk2(gv1, gv1);
            s30[0] = ffma2(gp0, wa.x, s30[0]);  s31[0] = ffma2(gp1, wa.x, s31[0]);
            s30[1] = ffma2(gp0, wa.y, s30[1]);  s31[1] = ffma2(gp1, wa.y, s31[1]);
            s30[2] = ffma2(gp0, wb.x, s30[2]);  s31[2] = ffma2(gp1, wb.x, s31[2]);
            s30[3] = ffma2(gp0, wb.y, s30[3]);  s31[3] = ffma2(gp1, wb.y, s31[3]);
        }

        // weighted accumulation with lifted features (packed)
        const ulonglong2* f0 = (const ulonglong2*)(g_f + ((size_t)(b * NPT + j0)) * 32 + cbase);
        const ulonglong2* f1 = (const ulonglong2*)(g_f + ((size_t)(b * NPT + j1)) * 32 + cbase);
        ulonglong2 fa0 = f0[0], fb0 = f0[1];
        ulonglong2 fa1 = f1[0], fb1 = f1[1];
        u64 pw0p = pk2(pw0, pw0), pw1p = pk2(pw1, pw1);
        accp[0] = ffma2(s30[0], fmul2(fa0.x, pw0p), accp[0]);
        accp[1] = ffma2(s30[1], fmul2(fa0.y, pw0p), accp[1]);
        accp[2] = ffma2(s30[2], fmul2(fb0.x, pw0p), accp[2]);
        accp[3] = ffma2(s30[3], fmul2(fb0.y, pw0p), accp[3]);
        accp[0] = ffma2(s31[0], fmul2(fa1.x, pw1p), accp[0]);
        accp[1] = ffma2(s31[1], fmul2(fa1.y, pw1p), accp[1]);
        accp[2] = ffma2(s31[2], fmul2(fb1.x, pw1p), accp[2]);
        accp[3] = ffma2(s31[3], fmul2(fb1.y, pw1p), accp[3]);
    }

    // ---- deterministic reduction: butterfly over the 8 quads in each warp ----
    float acc[8];
#pragma unroll
    for (int q = 0; q < 4; q++) upk2(accp[q], acc[2*q], acc[2*q+1]);
#pragma unroll
    for (int c = 0; c < 8; c++) {
        float v = acc[c];
        v += __shfl_xor_sync(0xffffffffu, v, 4);
        v += __shfl_xor_sync(0xffffffffu, v, 8);
        v += __shfl_xor_sync(0xffffffffu, v, 16);
        if (lane < 4) swred[wid][cbase + c] = v;
    }
    __syncthreads();
    if (tid < 32)
        out[bi * 32 + tid] = swred[0][tid] + swred[1][tid];
}

extern "C" void kernel_launch(void* const* d_in, const int* in_sizes, int n_in,
                              void* d_out, int out_size) {
    const float* x_coord = (const float*)d_in[0];
    const float* pndata  = (const float*)d_in[1];
    const float* ltc     = (const float*)d_in[2];
    const float* W_lift  = (const float*)d_in[3];
    const float* b_lift  = (const float*)d_in[4];
    const float* kW1     = (const float*)d_in[5];
    const float* kb1     = (const float*)d_in[6];
    const float* kW2     = (const float*)d_in[7];
    const float* kb2     = (const float*)d_in[8];
    const float* kW3     = (const float*)d_in[9];
    const float* kb3     = (const float*)d_in[10];
    float* out = (float*)d_out;

    lift_kernel<<<(NB * NPT * CCH + 255) / 256, 256>>>(pndata, W_lift, b_lift);
    agg_kernel<<<NB * NLAT, 64>>>(x_coord, ltc, kW1, kb1, kW2, kb2, kW3, kb3, out);
}